// round 17
// baseline (speedup 1.0000x reference)
#include <cuda_runtime.h>
#include <math.h>

// ---------------------------------------------------------------------------
// FCOS head v8: Winograd F(2x2,3x3) towers.
//  conv3x3 = input transform (BtdB) -> 16 pointwise GEMMs (FFMA2) -> output
//  transform (AtMA, fused GN stats). 2.25x fewer MACs than direct conv.
//  GN finalize/apply and pred kernels carried verbatim from v7 (passing).
// ---------------------------------------------------------------------------

#define CHN   256
#define CW    (256*256*9)
#define CICH  8
#define STOT  13343

// Winograd tile tables (per level): H, tilesY, valid tiles T, padded TP
//   HS  = {100,50,25,13,7}
//   TY  = {50,25,13,7,4}
//   T   = {2500,625,169,49,16}
//   TP  = {2500,640,176,64,16}   (mult of 16 -> cp.async 16B alignment)
//   PTP = {0,2500,3140,3316,3380}, total 3396
#define VSZ (16384*3396 + 8192)

__device__ float g_bufA[4 * CHN * STOT];
__device__ float g_bufB[4 * CHN * STOT];
__device__ float g_V[VSZ];          // transform-domain input  [slot][ci][t16][tile]
__device__ float g_D[VSZ];          // transform-domain output [slot][co][t16][tile]
__device__ float g_U[8*4*16*256*32*2]; // weights [wset][cb][t16][ci][cp] float2-as-floats
__device__ float g_stats[1280];
__device__ float g_nsc[5120];
__device__ float g_nsh[5120];

struct Feat5 { const float* p[5]; };

__global__ void zero_k(float* s) {
    for (int i = threadIdx.x; i < 1280; i += 256) s[i] = 0.f;
}

__device__ __forceinline__ void fma2(unsigned long long& d,
                                     unsigned long long a,
                                     unsigned long long b) {
    asm("fma.rn.f32x2 %0, %1, %2, %0;" : "+l"(d) : "l"(a), "l"(b));
}
__device__ __forceinline__ unsigned long long dup2(float v) {
    unsigned long long d;
    asm("mov.b64 %0, {%1, %1};" : "=l"(d) : "f"(v));
    return d;
}
__device__ __forceinline__ float2 up2(unsigned long long v) {
    float2 f;
    asm("mov.b64 {%0, %1}, %2;" : "=f"(f.x), "=f"(f.y) : "l"(v));
    return f;
}
__device__ __forceinline__ unsigned smem_u32(const void* p) {
    return (unsigned)__cvta_generic_to_shared(p);
}
#define CP_A16(dst, src) asm volatile("cp.async.ca.shared.global [%0],[%1],16;" :: "r"(dst), "l"(src))
#define CP_COMMIT        asm volatile("cp.async.commit_group;" ::: "memory")
#define CP_WAIT1         asm volatile("cp.async.wait_group 1;" ::: "memory")
#define CP_WAIT0         asm volatile("cp.async.wait_group 0;" ::: "memory")

// ---------------------------------------------------------------------------
// Weight transform: U = G g G^T per (wset, co, ci). One thread each.
// U layout (floats): ((((wset*4+cb)*16+t16)*256+ci)*32+cp)*2 + (co&1)
// ---------------------------------------------------------------------------
__global__ void wu_k(const float* __restrict__ cls_w,
                     const float* __restrict__ box_w,
                     float* __restrict__ Uf)
{
    const int idx = blockIdx.x * 256 + threadIdx.x;   // 2048 blocks
    const int wset = idx >> 16;
    const int r    = idx & 65535;
    const int co   = r >> 8;
    const int ci   = r & 255;

    const float* w = ((wset & 1) ? box_w : cls_w) + (size_t)(wset >> 1) * CW
                     + ((size_t)co * 256 + ci) * 9;
    float g[3][3];
#pragma unroll
    for (int i = 0; i < 3; i++)
#pragma unroll
        for (int j = 0; j < 3; j++) g[i][j] = w[i * 3 + j];

    float q[4][3];
#pragma unroll
    for (int j = 0; j < 3; j++) {
        q[0][j] = g[0][j];
        q[1][j] = 0.5f * (g[0][j] + g[1][j] + g[2][j]);
        q[2][j] = 0.5f * (g[0][j] - g[1][j] + g[2][j]);
        q[3][j] = g[2][j];
    }
    float u[4][4];
#pragma unroll
    for (int i = 0; i < 4; i++) {
        u[i][0] = q[i][0];
        u[i][1] = 0.5f * (q[i][0] + q[i][1] + q[i][2]);
        u[i][2] = 0.5f * (q[i][0] - q[i][1] + q[i][2]);
        u[i][3] = q[i][2];
    }
    const int cb = co >> 6, cp = (co & 63) >> 1, half = co & 1;
#pragma unroll
    for (int i = 0; i < 4; i++)
#pragma unroll
        for (int j = 0; j < 4; j++) {
            const int t16 = i * 4 + j;
            Uf[((((size_t)(wset * 4 + cb) * 16 + t16) * 256 + ci) * 32 + cp) * 2 + half]
                = u[i][j];
        }
}

// ---------------------------------------------------------------------------
// Input transform: V = Bt d B per (slot, ci, tile). grid (108, 32, 4).
// warp = ci (by*8+wid), lane = tile within 32-chunk.
// ---------------------------------------------------------------------------
template<bool FIRST>
__global__ __launch_bounds__(256)
void wint_k(Feat5 fp, const float* __restrict__ bufN, float* __restrict__ V)
{
    const int tid = threadIdx.x;
    const int wid = tid >> 5, ln = tid & 31;
    const int bx = blockIdx.x;
    int l = 0;
    if (bx >= 79)  l = 1;
    if (bx >= 99)  l = 2;
    if (bx >= 105) l = 3;
    if (bx >= 107) l = 4;
    const int HSs[5] = {100, 50, 25, 13, 7};
    const int TYs[5] = {50, 25, 13, 7, 4};
    const int Ts[5]  = {2500, 625, 169, 49, 16};
    const int TPs[5] = {2500, 640, 176, 64, 16};
    const int PTP[5] = {0, 2500, 3140, 3316, 3380};
    const int CB[5]  = {0, 79, 99, 105, 107};
    const int PB[5]  = {0, 10000, 12500, 13125, 13294};
    const int H = HSs[l], W = H, HW = H * W;
    const int tY = TYs[l], T = Ts[l], TP = TPs[l];

    const int slot = blockIdx.z;          // tw*2+b
    const int b = slot & 1;
    const int ci = blockIdx.y * 8 + wid;
    const int tile = (bx - CB[l]) * 32 + ln;
    if (tile >= T) return;

    const float* src = FIRST
        ? fp.p[l] + ((size_t)b * CHN + ci) * HW
        : bufN + (size_t)1024 * PB[l] + (size_t)(slot * 256 + ci) * HW;

    const int ty = tile / tY, tx = tile - ty * tY;
    const int y0 = 2 * ty - 1, x0 = 2 * tx - 1;

    float d[4][4];
#pragma unroll
    for (int i = 0; i < 4; i++) {
        const int y = y0 + i;
        const bool yok = (unsigned)y < (unsigned)H;
#pragma unroll
        for (int j = 0; j < 4; j++) {
            const int x = x0 + j;
            d[i][j] = (yok && (unsigned)x < (unsigned)W) ? src[y * W + x] : 0.f;
        }
    }
    float t[4][4], v[4][4];
#pragma unroll
    for (int j = 0; j < 4; j++) {
        t[0][j] = d[0][j] - d[2][j];
        t[1][j] = d[1][j] + d[2][j];
        t[2][j] = d[2][j] - d[1][j];
        t[3][j] = d[1][j] - d[3][j];
    }
#pragma unroll
    for (int i = 0; i < 4; i++) {
        v[i][0] = t[i][0] - t[i][2];
        v[i][1] = t[i][1] + t[i][2];
        v[i][2] = t[i][2] - t[i][1];
        v[i][3] = t[i][1] - t[i][3];
    }
    const int base = 16384 * PTP[l] + ((slot * 256 + ci) * 16) * TP + tile;
#pragma unroll
    for (int t16 = 0; t16 < 16; t16++)
        V[base + t16 * TP] = v[t16 >> 2][t16 & 3];
}

// ---------------------------------------------------------------------------
// Transform-domain GEMM: D[co,tile] += U[co,ci] * V[ci,tile], K=256.
// grid (21 tile-chunks, 4 co-blocks, 64 = t16*4 + slot). block 256.
// Block tile: 64 co x 192 tiles. warp = 8 co, thread = 4 co-pair x 6 tiles.
// ---------------------------------------------------------------------------
__global__ __launch_bounds__(256, 2)
void wgemm_k(const float* __restrict__ V, float* __restrict__ D,
             const float* __restrict__ U, int layer)
{
    extern __shared__ __align__(16) char smem[];   // 2 stages x (12288 V + 4096 U)

    const int tid = threadIdx.x;
    const int bx = blockIdx.x;
    int l = 0;
    if (bx >= 14) l = 1;
    if (bx >= 18) l = 2;
    if (bx >= 19) l = 3;
    if (bx >= 20) l = 4;
    const int Ts[5]  = {2500, 625, 169, 49, 16};
    const int TPs[5] = {2500, 640, 176, 64, 16};
    const int PTP[5] = {0, 2500, 3140, 3316, 3380};
    const int GB[5]  = {0, 14, 18, 19, 20};
    const int T = Ts[l], TP = TPs[l];
    const int c0 = (bx - GB[l]) * 192;

    const int slot = blockIdx.z & 3;
    const int t16  = blockIdx.z >> 2;
    const int tw   = slot >> 1;
    const int wset = layer * 2 + tw;
    const int cb   = blockIdx.y;
    const int VOFF = 16384 * PTP[l];

    const int wid = tid >> 5, ln = tid & 31;

    // global row bases
    // V row(ci): VOFF + ((slot*256+ci)*16 + t16)*TP + c0   (floats)
    // U chunk(ci0): (((wset*4+cb)*16+t16)*256 + ci0)*32 float2 -> *2 floats
    const size_t vrow0 = (size_t)VOFF + ((size_t)(slot * 256) * 16 + t16) * TP + c0;
    const size_t ubase0 = (((size_t)(wset * 4 + cb) * 16 + t16) * 256) * 64;

    const unsigned sb0 = smem_u32(smem);

    unsigned long long acc[4][6];
#pragma unroll
    for (int i = 0; i < 4; i++)
#pragma unroll
        for (int j = 0; j < 6; j++) acc[i][j] = 0ull;

    auto issue_stage = [&](int kc) {
        const unsigned sbase = sb0 + (kc & 1) * 16384;
        const int ci0 = kc * 16;
        // V: 16 rows x 192 floats = 16 x 48 x 16B
#pragma unroll 1
        for (int i = tid; i < 768; i += 256) {
            const int row = i / 48;
            const int rem = i - row * 48;
            const float* src = V + vrow0 + (size_t)(ci0 + row) * 16 * TP + rem * 4;
            CP_A16(sbase + row * 768 + rem * 16, src);
        }
        // U: 16 rows x 32 float2 = 256 x 16B
        {
            const float* src = U + ubase0 + (size_t)ci0 * 64 + tid * 4;
            CP_A16(sbase + 12288 + tid * 16, src);
        }
        CP_COMMIT;
    };

    issue_stage(0);

    for (int kc = 0; kc < 16; kc++) {
        if (kc + 1 < 16) { issue_stage(kc + 1); CP_WAIT1; }
        else             { CP_WAIT0; }
        __syncthreads();

        const char* sb = smem + (kc & 1) * 16384;
#pragma unroll 1
        for (int k = 0; k < 16; k++) {
            const float* Vk = (const float*)(sb + k * 768);
            unsigned long long vv[6];
#pragma unroll
            for (int j = 0; j < 6; j++) vv[j] = dup2(Vk[j * 32 + ln]);
            const ulonglong2* Uk = (const ulonglong2*)(sb + 12288 + k * 256) + (wid << 1);
            const ulonglong2 wA = Uk[0];
            const ulonglong2 wB = Uk[1];
#pragma unroll
            for (int j = 0; j < 6; j++) {
                fma2(acc[0][j], wA.x, vv[j]);
                fma2(acc[1][j], wA.y, vv[j]);
                fma2(acc[2][j], wB.x, vv[j]);
                fma2(acc[3][j], wB.y, vv[j]);
            }
        }
        __syncthreads();
    }

    // epilogue: D[slot][co][t16][tile]
    const int coB = cb * 64 + wid * 8;
#pragma unroll
    for (int j = 0; j < 6; j++) {
        const int tile = c0 + j * 32 + ln;
        if (tile < T) {
#pragma unroll
            for (int cp = 0; cp < 4; cp++) {
                const float2 f = up2(acc[cp][j]);
                const int co = coB + 2 * cp;
                const size_t di = (size_t)VOFF + ((size_t)(slot * 256 + co) * 16 + t16) * TP + tile;
                D[di]      = f.x;
                D[di + (size_t)16 * TP] = f.y;   // co+1 row
            }
        }
    }
}

// ---------------------------------------------------------------------------
// Output transform: O = At M A per (slot, co, tile); writes raw conv output
// + GN group stats. grid (29, 32, 4). warp = co (by*8+wid), lanes = tiles.
// ---------------------------------------------------------------------------
__global__ __launch_bounds__(256)
void wout_k(const float* __restrict__ D, float* __restrict__ bufRaw,
            float* __restrict__ stats)
{
    const int tid = threadIdx.x;
    const int wid = tid >> 5, ln = tid & 31;
    const int bx = blockIdx.x;
    int l = 0;
    if (bx >= 20) l = 1;
    if (bx >= 25) l = 2;
    if (bx >= 27) l = 3;
    if (bx >= 28) l = 4;
    const int HSs[5] = {100, 50, 25, 13, 7};
    const int TYs[5] = {50, 25, 13, 7, 4};
    const int Ts[5]  = {2500, 625, 169, 49, 16};
    const int TPs[5] = {2500, 640, 176, 64, 16};
    const int PTP[5] = {0, 2500, 3140, 3316, 3380};
    const int WB[5]  = {0, 20, 25, 27, 28};
    const int PB[5]  = {0, 10000, 12500, 13125, 13294};
    const int H = HSs[l], W = H, HW = H * W;
    const int tY = TYs[l], T = Ts[l], TP = TPs[l];

    const int slot = blockIdx.z;
    const int co = blockIdx.y * 8 + wid;
    const size_t drow = (size_t)16384 * PTP[l] + ((size_t)(slot * 256 + co) * 16) * TP;
    float* outb = bufRaw + (size_t)1024 * PB[l] + (size_t)(slot * 256 + co) * HW;

    float s = 0.f, ss = 0.f;
#pragma unroll 1
    for (int it = 0; it < 4; it++) {
        const int tile = (bx - WB[l]) * 128 + it * 32 + ln;
        if (tile < T) {
            float m[4][4];
#pragma unroll
            for (int t16 = 0; t16 < 16; t16++)
                m[t16 >> 2][t16 & 3] = D[drow + (size_t)t16 * TP + tile];
            float s0[4], s1[4];
#pragma unroll
            for (int j = 0; j < 4; j++) {
                s0[j] = m[0][j] + m[1][j] + m[2][j];
                s1[j] = m[1][j] - m[2][j] - m[3][j];
            }
            float o[2][2];
            o[0][0] = s0[0] + s0[1] + s0[2];
            o[0][1] = s0[1] - s0[2] - s0[3];
            o[1][0] = s1[0] + s1[1] + s1[2];
            o[1][1] = s1[1] - s1[2] - s1[3];

            const int ty = tile / tY, tx = tile - ty * tY;
#pragma unroll
            for (int dy = 0; dy < 2; dy++) {
                const int y = 2 * ty + dy;
                if (y < H) {
#pragma unroll
                    for (int dx = 0; dx < 2; dx++) {
                        const int x = 2 * tx + dx;
                        if (x < W) {
                            const float vv = o[dy][dx];
                            outb[y * W + x] = vv;
                            s += vv;
                            ss = fmaf(vv, vv, ss);
                        }
                    }
                }
            }
        }
    }
#pragma unroll
    for (int o2 = 16; o2 > 0; o2 >>= 1) {
        s  += __shfl_xor_sync(0xffffffffu, s,  o2);
        ss += __shfl_xor_sync(0xffffffffu, ss, o2);
    }
    if (ln == 0) {
        const int sslot = l * 4 + slot;
        atomicAdd(&stats[sslot * 64 + (co >> 3) * 2],     s);
        atomicAdd(&stats[sslot * 64 + (co >> 3) * 2 + 1], ss);
    }
}

// ---------------------------------------------------------------------------
// finalize GN (unchanged from v7)
// ---------------------------------------------------------------------------
__global__ void fin_k(const float* __restrict__ cg, const float* __restrict__ cb,
                      const float* __restrict__ bg, const float* __restrict__ bb,
                      float* __restrict__ stats,
                      float* __restrict__ nsc, float* __restrict__ nsh)
{
    const int slot = blockIdx.x;
    const int l  = slot >> 2;
    const int tw = (slot >> 1) & 1;
    const int c  = threadIdx.x;
    const int g  = c >> 3;
    const int HSs[5] = {100, 50, 25, 13, 7};
    const float invcnt = 1.f / (8.f * HSs[l] * HSs[l]);

    const float sum = stats[slot * 64 + g * 2];
    const float sq  = stats[slot * 64 + g * 2 + 1];
    const float mean = sum * invcnt;
    const float var  = fmaf(-mean, mean, sq * invcnt);
    const float rstd = rsqrtf(var + 1e-5f);
    const float* gam = tw ? bg : cg;
    const float* bet = tw ? bb : cb;
    const float sc = gam[c] * rstd;
    nsc[slot * 256 + c] = sc;
    nsh[slot * 256 + c] = fmaf(-mean, sc, bet[c]);
    __syncthreads();
    if (c < 64) stats[slot * 64 + c] = 0.f;
}

// ---------------------------------------------------------------------------
// GN apply (unchanged from v7)
// ---------------------------------------------------------------------------
__global__ __launch_bounds__(256)
void apply_k(const float* __restrict__ src, float* __restrict__ dst,
             const float* __restrict__ nsc, const float* __restrict__ nsh)
{
    const int f = blockIdx.x * 256 + threadIdx.x;
    const int N0 = 10240000, N1 = 12800000, N2 = 13440000, N3 = 13613056,
              N4 = 13663232;
    if (f >= N4) return;
    int nidx;
    if (f < N0)      { nidx =        (f)      / 10000; }
    else if (f < N1) { nidx = 1024 + (f - N0) / 2500;  }
    else if (f < N2) { nidx = 2048 + (f - N1) / 625;   }
    else if (f < N3) { nidx = 3072 + (f - N2) / 169;   }
    else             { nidx = 4096 + (f - N3) / 49;    }
    dst[f] = fmaxf(fmaf(src[f], nsc[nidx], nsh[nidx]), 0.f);
}

// ---------------------------------------------------------------------------
// cls_pred(20) + ctr_pred(1) (unchanged from v7, passing)
// ---------------------------------------------------------------------------
__global__ __launch_bounds__(256)
void pred_cls_k(const float* __restrict__ bin,
                const float* __restrict__ clsw, const float* __restrict__ clsb,
                const float* __restrict__ ctrw, const float* __restrict__ ctrb,
                float* __restrict__ out)
{
    __shared__ __align__(16) float s_in[CICH][18][19];
    __shared__ __align__(16) float s_wk[CICH][9][24];

    const int tid = threadIdx.x;
    const int bx = blockIdx.x;
    int l = 0;
    if (bx >= 49) l = 1;
    if (bx >= 65) l = 2;
    if (bx >= 69) l = 3;
    if (bx >= 70) l = 4;
    const int HSs[5]   = {100, 50, 25, 13, 7};
    const int TBASE[5] = {0, 49, 65, 69, 70};
    const int TXN[5]   = {7, 4, 2, 1, 1};
    const int PB[5]    = {0, 10000, 12500, 13125, 13294};
    const int H = HSs[l], W = H, HW = H * W;
    const int t = bx - TBASE[l];
    const int tX = TXN[l];
    const int ty = t / tX, tx = t - ty * tX;
    const int y0 = ty * 16, x0 = tx * 16;
    const int b = blockIdx.z;
    const int ly = tid >> 4, lx = tid & 15;

    const float* inb = bin + (size_t)1024 * PB[l] + (size_t)((0 * 2 + b) * CHN) * HW;

    float acc[24];
#pragma unroll
    for (int k = 0; k < 24; k++) acc[k] = 0.f;
#pragma unroll
    for (int k = 0; k < 20; k++) acc[k] = clsb[k];
    acc[20] = ctrb[0];

    for (int ci0 = 0; ci0 < CHN; ci0 += CICH) {
#pragma unroll 1
        for (int j = tid; j < CICH * 18 * 18; j += 256) {
            int ci = j / 324;
            int r2 = j - ci * 324;
            int iy = r2 / 18, ix = r2 - iy * 18;
            int gy = y0 - 1 + iy, gx = x0 - 1 + ix;
            float v = 0.f;
            if ((unsigned)gy < (unsigned)H && (unsigned)gx < (unsigned)W)
                v = inb[(size_t)(ci0 + ci) * HW + gy * W + gx];
            s_in[ci][iy][ix] = v;
        }
#pragma unroll 1
        for (int j = tid; j < CICH * 216; j += 256) {
            int ci = j / 216;
            int r2 = j - ci * 216;
            int kk = r2 / 24;
            int k  = r2 - kk * 24;
            int c  = ci0 + ci;
            float v = 0.f;
            if (k < 20)       v = clsw[((size_t)k * CHN + c) * 9 + kk];
            else if (k == 20) v = ctrw[(size_t)c * 9 + kk];
            s_wk[ci][kk][k] = v;
        }
        __syncthreads();
#pragma unroll 2
        for (int ci = 0; ci < CICH; ci++) {
#pragma unroll
            for (int ky = 0; ky < 3; ky++)
#pragma unroll
                for (int kx = 0; kx < 3; kx++) {
                    const float v = s_in[ci][ly + ky][lx + kx];
#pragma unroll
                    for (int kq = 0; kq < 6; kq++) {
                        const float4 wv = *(const float4*)&s_wk[ci][ky * 3 + kx][kq << 2];
                        acc[kq * 4 + 0] = fmaf(v, wv.x, acc[kq * 4 + 0]);
                        acc[kq * 4 + 1] = fmaf(v, wv.y, acc[kq * 4 + 1]);
                        acc[kq * 4 + 2] = fmaf(v, wv.z, acc[kq * 4 + 2]);
                        acc[kq * 4 + 3] = fmaf(v, wv.w, acc[kq * 4 + 3]);
                    }
                }
        }
        __syncthreads();
    }

    const int gy = y0 + ly, gx = x0 + lx;
    if (gy < H && gx < W) {
        float* lg = out + (size_t)40 * PB[l];
#pragma unroll
        for (int k = 0; k < 20; k++)
            lg[((size_t)(b * 20 + k)) * HW + gy * W + gx] = acc[k];
        out[(size_t)48 * STOT + 2 * PB[l] + (size_t)b * HW + gy * W + gx] = acc[20];
    }
}

// ---------------------------------------------------------------------------
// box_pred(4) with exp(v*scale) (unchanged from v7, passing)
// ---------------------------------------------------------------------------
__global__ __launch_bounds__(256)
void pred_box_k(const float* __restrict__ bin,
                const float* __restrict__ boxw, const float* __restrict__ boxb,
                const float* __restrict__ scales, float* __restrict__ out)
{
    __shared__ __align__(16) float s_in[CICH][18][19];
    __shared__ __align__(16) float s_wk[CICH][9][4];

    const int tid = threadIdx.x;
    const int bx = blockIdx.x;
    int l = 0;
    if (bx >= 49) l = 1;
    if (bx >= 65) l = 2;
    if (bx >= 69) l = 3;
    if (bx >= 70) l = 4;
    const int HSs[5]   = {100, 50, 25, 13, 7};
    const int TBASE[5] = {0, 49, 65, 69, 70};
    const int TXN[5]   = {7, 4, 2, 1, 1};
    const int PB[5]    = {0, 10000, 12500, 13125, 13294};
    const int H = HSs[l], W = H, HW = H * W;
    const int t = bx - TBASE[l];
    const int tX = TXN[l];
    const int ty = t / tX, tx = t - ty * tX;
    const int y0 = ty * 16, x0 = tx * 16;
    const int b = blockIdx.z;
    const int ly = tid >> 4, lx = tid & 15;

    const float* inb = bin + (size_t)1024 * PB[l] + (size_t)((1 * 2 + b) * CHN) * HW;

    float acc[4];
#pragma unroll
    for (int k = 0; k < 4; k++) acc[k] = boxb[k];

    for (int ci0 = 0; ci0 < CHN; ci0 += CICH) {
#pragma unroll 1
        for (int j = tid; j < CICH * 18 * 18; j += 256) {
            int ci = j / 324;
            int r2 = j - ci * 324;
            int iy = r2 / 18, ix = r2 - iy * 18;
            int gy = y0 - 1 + iy, gx = x0 - 1 + ix;
            float v = 0.f;
            if ((unsigned)gy < (unsigned)H && (unsigned)gx < (unsigned)W)
                v = inb[(size_t)(ci0 + ci) * HW + gy * W + gx];
            s_in[ci][iy][ix] = v;
        }
#pragma unroll 1
        for (int j = tid; j < CICH * 36; j += 256) {
            int ci = j / 36;
            int r2 = j - ci * 36;
            int kk = r2 >> 2;
            int k  = r2 & 3;
            s_wk[ci][kk][k] = boxw[((size_t)k * CHN + ci0 + ci) * 9 + kk];
        }
        __syncthreads();
#pragma unroll 2
        for (int ci = 0; ci < CICH; ci++) {
#pragma unroll
            for (int ky = 0; ky < 3; ky++)
#pragma unroll
                for (int kx = 0; kx < 3; kx++) {
                    const float v = s_in[ci][ly + ky][lx + kx];
                    const float4 wv = *(const float4*)&s_wk[ci][ky * 3 + kx][0];
                    acc[0] = fmaf(v, wv.x, acc[0]);
                    acc[1] = fmaf(v, wv.y, acc[1]);
                    acc[2] = fmaf(v, wv.z, acc[2]);
                    acc[3] = fmaf(v, wv.w, acc[3]);
                }
        }
        __syncthreads();
    }

    const int gy = y0 + ly, gx = x0 + lx;
    if (gy < H && gx < W) {
        const float scl = scales[l];
        float* bo = out + (size_t)40 * STOT + 8 * PB[l];
#pragma unroll
        for (int k = 0; k < 4; k++)
            bo[((size_t)(b * 4 + k)) * HW + gy * W + gx] = expf(acc[k] * scl);
    }
}

// ---------------------------------------------------------------------------
extern "C" void kernel_launch(void* const* d_in, const int* in_sizes, int n_in,
                              void* d_out, int out_size)
{
    (void)in_sizes; (void)n_in; (void)out_size;

    Feat5 fp;
    for (int i = 0; i < 5; i++) fp.p[i] = (const float*)d_in[i];
    const float* cls_w  = (const float*)d_in[5];
    const float* cls_g  = (const float*)d_in[6];
    const float* cls_b  = (const float*)d_in[7];
    const float* box_w  = (const float*)d_in[8];
    const float* box_g  = (const float*)d_in[9];
    const float* box_b  = (const float*)d_in[10];
    const float* clsp_w = (const float*)d_in[11];
    const float* clsp_b = (const float*)d_in[12];
    const float* boxp_w = (const float*)d_in[13];
    const float* boxp_b = (const float*)d_in[14];
    const float* ctrp_w = (const float*)d_in[15];
    const float* ctrp_b = (const float*)d_in[16];
    const float* scales = (const float*)d_in[17];
    float* out = (float*)d_out;

    float *bufA, *bufB, *stats, *nsc, *nsh, *V, *D, *U;
    cudaGetSymbolAddress((void**)&bufA,  g_bufA);
    cudaGetSymbolAddress((void**)&bufB,  g_bufB);
    cudaGetSymbolAddress((void**)&V,     g_V);
    cudaGetSymbolAddress((void**)&D,     g_D);
    cudaGetSymbolAddress((void**)&U,     g_U);
    cudaGetSymbolAddress((void**)&stats, g_stats);
    cudaGetSymbolAddress((void**)&nsc,   g_nsc);
    cudaGetSymbolAddress((void**)&nsh,   g_nsh);

    cudaFuncSetAttribute(wgemm_k, cudaFuncAttributeMaxDynamicSharedMemorySize, 32768);

    const dim3 gint(108, 32, 4);
    const dim3 ggemm(21, 4, 64);
    const dim3 gout(29, 32, 4);
    const dim3 gpred(71, 1, 2);
    const int  gapply = (13663232 + 255) / 256;

    zero_k<<<1, 256>>>(stats);
    wu_k<<<2048, 256>>>(cls_w, box_w, U);

    // layer 0
    wint_k<true ><<<gint, 256>>>(fp, bufB, V);
    wgemm_k<<<ggemm, 256, 32768>>>(V, D, U, 0);
    wout_k<<<gout, 256>>>(D, bufA, stats);
    fin_k<<<20, 256>>>(cls_g,       cls_b,       box_g,       box_b,       stats, nsc, nsh);
    apply_k<<<gapply, 256>>>(bufA, bufB, nsc, nsh);
    // layer 1
    wint_k<false><<<gint, 256>>>(fp, bufB, V);
    wgemm_k<<<ggemm, 256, 32768>>>(V, D, U, 1);
    wout_k<<<gout, 256>>>(D, bufA, stats);
    fin_k<<<20, 256>>>(cls_g + 256, cls_b + 256, box_g + 256, box_b + 256, stats, nsc, nsh);
    apply_k<<<gapply, 256>>>(bufA, bufB, nsc, nsh);
    // layer 2
    wint_k<false><<<gint, 256>>>(fp, bufB, V);
    wgemm_k<<<ggemm, 256, 32768>>>(V, D, U, 2);
    wout_k<<<gout, 256>>>(D, bufA, stats);
    fin_k<<<20, 256>>>(cls_g + 512, cls_b + 512, box_g + 512, box_b + 512, stats, nsc, nsh);
    apply_k<<<gapply, 256>>>(bufA, bufB, nsc, nsh);
    // layer 3
    wint_k<false><<<gint, 256>>>(fp, bufB, V);
    wgemm_k<<<ggemm, 256, 32768>>>(V, D, U, 3);
    wout_k<<<gout, 256>>>(D, bufA, stats);
    fin_k<<<20, 256>>>(cls_g + 768, cls_b + 768, box_g + 768, box_b + 768, stats, nsc, nsh);
    apply_k<<<gapply, 256>>>(bufA, bufB, nsc, nsh);

    pred_cls_k<<<gpred, 256>>>(bufB, clsp_w, clsp_b, ctrp_w, ctrp_b, out);
    pred_box_k<<<gpred, 256>>>(bufB, boxp_w, boxp_b, scales, out);
}